// round 3
// baseline (speedup 1.0000x reference)
#include <cuda_runtime.h>

// ExponentialMovingAverage: y_t = (1-a)*y_{t-1} + a*x_t, a=0.9, y_{-1}=0
// x: [B=16, T=4000, C=512] fp32 -> y same shape.
//
// Strategy: time-chunked parallel scan. Decay factor (1-a)=0.1 means the
// influence of x_{t-k} on y_t is 0.9*0.1^k; after K=10 steps this is 1e-10,
// far below the 1e-3 rel-err gate and below fp32 ulp of a unit-scale signal.
// Each thread owns one (b, channel-quad, time-chunk of L=80), warm-starts
// with a K-step truncated recurrence over the preceding inputs (exact when
// the chunk starts at t=0), then runs the exact recurrence for L steps,
// writing every output. Read amplification: (L+K)/L = 1.125x.
// 102400 threads -> ~21.6 warps/SM, single wave: enough MLP to saturate HBM.

#define B_DIM 16
#define T_DIM 4000
#define C_DIM 512
#define C4    (C_DIM / 4)       // 128 float4 per row
#define LCHUNK 80
#define NCHUNK (T_DIM / LCHUNK) // 50
#define KWARM 10

__global__ __launch_bounds__(256, 8)
void ema_kernel(const float* __restrict__ x, float* __restrict__ y) {
    const float A   = 0.9f;
    const float OMA = 0.1f;   // 1 - 0.9 (fp32-rounded, matches reference)

    int tid = blockIdx.x * blockDim.x + threadIdx.x;
    // c4: bits [0,7) ; b: bits [7,11) ; chunk: bits [11,...)
    int c4    = tid & (C4 - 1);
    int b     = (tid >> 7) & (B_DIM - 1);
    int chunk = tid >> 11;
    if (chunk >= NCHUNK) return;

    const int t0 = chunk * LCHUNK;

    const float4* __restrict__ xp =
        reinterpret_cast<const float4*>(x) + (size_t)b * T_DIM * C4 + c4;
    float4* __restrict__ yp =
        reinterpret_cast<float4*>(y) + (size_t)b * T_DIM * C4 + c4;

    float4 acc = make_float4(0.f, 0.f, 0.f, 0.f);

    // Warm-up: truncated recurrence over up to KWARM preceding steps.
    // For chunk 0 this loop runs over [0, 0) -> exact zero init.
    int tw = t0 - KWARM;
    if (tw < 0) tw = 0;
    const float4* p = xp + (size_t)tw * C4;
    #pragma unroll 5
    for (int t = tw; t < t0; ++t) {
        float4 v = __ldg(p);
        p += C4;
        acc.x = fmaf(OMA, acc.x, A * v.x);
        acc.y = fmaf(OMA, acc.y, A * v.y);
        acc.z = fmaf(OMA, acc.z, A * v.z);
        acc.w = fmaf(OMA, acc.w, A * v.w);
    }

    // Main chunk: exact recurrence, write every output. Unroll 8 so ptxas
    // front-batches 8 independent LDG.E.128 per iteration group (MLP=8);
    // the dependent FMA chain hides under the load latency.
    const float4* __restrict__ pin  = xp + (size_t)t0 * C4;
    float4* __restrict__ pout = yp + (size_t)t0 * C4;
    #pragma unroll 8
    for (int t = 0; t < LCHUNK; ++t) {
        float4 v = __ldg(pin + (size_t)t * C4);
        acc.x = fmaf(OMA, acc.x, A * v.x);
        acc.y = fmaf(OMA, acc.y, A * v.y);
        acc.z = fmaf(OMA, acc.z, A * v.z);
        acc.w = fmaf(OMA, acc.w, A * v.w);
        pout[(size_t)t * C4] = acc;
    }
}

extern "C" void kernel_launch(void* const* d_in, const int* in_sizes, int n_in,
                              void* d_out, int out_size) {
    (void)in_sizes; (void)n_in; (void)out_size;
    const float* x = (const float*)d_in[0];
    float* y = (float*)d_out;

    const int total_threads = NCHUNK * B_DIM * C4;  // 50*16*128 = 102400
    const int block = 256;
    const int grid = (total_threads + block - 1) / block;  // 400
    ema_kernel<<<grid, block>>>(x, y);
}